// round 12
// baseline (speedup 1.0000x reference)
#include <cuda_runtime.h>
#include <stdint.h>

// Problem constants (fixed by the reference)
#define NXD 512
#define NYD 512
#define CH  128
#define QCH 32                          // channels per quarter
#define BATCH 4
#define CELLS (NYD * NXD)               // 262144 cells per batch
#define TOTAL_CELLS (BATCH * CELLS)     // 1,048,576  (= 1<<20)
#define TILE_CELLS 128                  // cells per CTA tile
#define NGROUPS (TOTAL_CELLS / TILE_CELLS)   // 8192

// Scratch: per-cell pillar index, reset to -1 each call via a 0xFF memset node.
__device__ int g_idx[TOTAL_CELLS];
// Zero feature row (512B) for empty cells -> one hot L1/L2 line, broadcast.
__device__ float4 g_zero_row[CH / 4];

// ---------------------------------------------------------------------------
// Pass 1: scatter pillar index into canvas. coords row = [b, z, y, x], NZ=1.
// ---------------------------------------------------------------------------
__global__ void build_idx_kernel(const int* __restrict__ coords, int P) {
    int p = blockIdx.x * blockDim.x + threadIdx.x;
    if (p >= P) return;
    int4 c = ((const int4*)coords)[p];               // b, z, y, x
    int cell = (c.x + c.y) * CELLS + c.z * NXD + c.w;
    g_idx[cell] = p;
}

// ---------------------------------------------------------------------------
// Pass 2: gather with SMEM transpose staging.
// CTA tile = 128 consecutive x-cells x 32 channels (quarter q).
//  Phase A: 8 lanes per row-quarter -> every warp LDG.128 covers 4 fully-
//           consumed 128B lines (coalesced reads; no divergence amplification).
//           STS into a 33-float padded tile (bank-conflict-free by bijection).
//  Phase B: warp = one channel; 32 lanes x float4 over 128 consecutive cells
//           -> each store warp-instr is 512 contiguous bytes in one plane.
// ---------------------------------------------------------------------------
__global__ __launch_bounds__(256) void gather_kernel(
    const float* __restrict__ feat, float* __restrict__ out)
{
    __shared__ int   s_p[TILE_CELLS];
    __shared__ float s_tile[TILE_CELLS][QCH + 1];    // +1 pad: 33 floats/row

    int blk  = blockIdx.x;
    int grp  = blk & (NGROUPS - 1);                  // cell-group: FAST dim
    int q    = blk >> 13;                            // channel quarter 0..3
    int cell0 = grp * TILE_CELLS;
    int t = threadIdx.x;

    if (t < TILE_CELLS) s_p[t] = __ldg(g_idx + cell0 + t);
    __syncthreads();

    // ---- Phase A: load 128 row-quarters (128B each), front-batched ----
    int chunk = t & 7;                               // 16B chunk within quarter
    int rbase = t >> 3;                              // 0..31

    float4 v0, v1, v2, v3;
    {
        int p0 = s_p[rbase];
        int p1 = s_p[32 + rbase];
        int p2 = s_p[64 + rbase];
        int p3 = s_p[96 + rbase];
        const float4* z = (const float4*)g_zero_row + chunk;
        const float4* a0 = (p0 >= 0) ? (const float4*)(feat + (size_t)p0 * CH + q * QCH) + chunk : z;
        const float4* a1 = (p1 >= 0) ? (const float4*)(feat + (size_t)p1 * CH + q * QCH) + chunk : z;
        const float4* a2 = (p2 >= 0) ? (const float4*)(feat + (size_t)p2 * CH + q * QCH) + chunk : z;
        const float4* a3 = (p3 >= 0) ? (const float4*)(feat + (size_t)p3 * CH + q * QCH) + chunk : z;
        v0 = __ldg(a0); v1 = __ldg(a1); v2 = __ldg(a2); v3 = __ldg(a3);
    }
    {
        float* d0 = &s_tile[rbase     ][chunk * 4];
        float* d1 = &s_tile[32 + rbase][chunk * 4];
        float* d2 = &s_tile[64 + rbase][chunk * 4];
        float* d3 = &s_tile[96 + rbase][chunk * 4];
        d0[0]=v0.x; d0[1]=v0.y; d0[2]=v0.z; d0[3]=v0.w;
        d1[0]=v1.x; d1[1]=v1.y; d1[2]=v1.z; d1[3]=v1.w;
        d2[0]=v2.x; d2[1]=v2.y; d2[2]=v2.z; d2[3]=v2.w;
        d3[0]=v3.x; d3[1]=v3.y; d3[2]=v3.z; d3[3]=v3.w;
    }
    __syncthreads();

    // ---- Phase B: transpose out of SMEM, 512B contiguous warp stores ----
    int w    = t >> 5;                               // warp 0..7
    int lane = t & 31;
    int b  = cell0 >> 18;                            // batch
    int xy = cell0 & (CELLS - 1);                    // y*512 + x within batch
    float* obq = out + ((size_t)b * CH + q * QCH) * CELLS + xy + 4 * lane;

    #pragma unroll
    for (int cc = 0; cc < 4; ++cc) {
        int c = w * 4 + cc;                          // channel within quarter
        float4 ov = make_float4(s_tile[4 * lane + 0][c],
                                s_tile[4 * lane + 1][c],
                                s_tile[4 * lane + 2][c],
                                s_tile[4 * lane + 3][c]);
        *(float4*)(obq + (size_t)c * CELLS) = ov;
    }
}

// ---------------------------------------------------------------------------
// Launch: identify inputs by size (batch_size scalar / features / coords).
// ---------------------------------------------------------------------------
extern "C" void kernel_launch(void* const* d_in, const int* in_sizes, int n_in,
                              void* d_out, int out_size)
{
    // features is the largest input (P*128 floats); coords has P*4 ints.
    int fi = 0;
    long long best = -1;
    for (int i = 0; i < n_in; ++i) {
        if ((long long)in_sizes[i] > best) { best = in_sizes[i]; fi = i; }
    }
    const float* feat = (const float*)d_in[fi];
    int P = in_sizes[fi] / CH;

    const int* coords = nullptr;
    for (int i = 0; i < n_in; ++i) {
        if (i != fi && in_sizes[i] == P * 4) { coords = (const int*)d_in[i]; break; }
    }
    if (!coords) { // fallback: second-largest input
        int ci = -1; long long b2 = -1;
        for (int i = 0; i < n_in; ++i)
            if (i != fi && (long long)in_sizes[i] > b2) { b2 = in_sizes[i]; ci = i; }
        coords = (const int*)d_in[ci];
    }

    float* out = (float*)d_out;

    // Pass 0: reset index canvas to -1 (0xFF bytes). Memset node: capturable.
    void* idx_ptr = nullptr;
    cudaGetSymbolAddress(&idx_ptr, g_idx);
    cudaMemsetAsync(idx_ptr, 0xFF, TOTAL_CELLS * sizeof(int), 0);

    // Pass 1: scatter pillar indices
    build_idx_kernel<<<(P + 255) / 256, 256>>>(coords, P);

    // Pass 2: SMEM-staged gather + transpose (32768 CTAs)
    gather_kernel<<<NGROUPS * 4, 256>>>(feat, out);
}

// round 13
// speedup vs baseline: 1.1703x; 1.1703x over previous
#include <cuda_runtime.h>
#include <stdint.h>

// Problem constants (fixed by the reference)
#define NXD 512
#define NYD 512
#define CH  128
#define QCH 32                          // channels per thread (quarter row)
#define BATCH 4
#define CELLS (NYD * NXD)               // 262144 cells per batch
#define TOTAL_CELLS (BATCH * CELLS)     // 1,048,576  (= 1<<20)

// Scratch: per-cell pillar index, reset to -1 each call via a 0xFF memset node.
__device__ int g_idx[TOTAL_CELLS];
// Zero feature row for empty cells (zero-initialized, read-only -> hot in L2).
__device__ float4 g_zero_row[CH / 4];

// ---------------------------------------------------------------------------
// Pass 1: scatter pillar index into canvas. coords row = [b, z, y, x], NZ=1.
// ---------------------------------------------------------------------------
__global__ void build_idx_kernel(const int* __restrict__ coords, int P) {
    int p = blockIdx.x * blockDim.x + threadIdx.x;
    if (p >= P) return;
    int4 c = ((const int4*)coords)[p];               // b, z, y, x
    int cell = (c.x + c.y) * CELLS + c.z * NXD + c.w;
    g_idx[cell] = p;
}

// ---------------------------------------------------------------------------
// Pass 2: gather (R8 structure — best measured). FOUR threads per cell, each
// owning 32 channels (one quarter row = exactly one 128B feature line).
// Quarter selected by high grid bits -> consecutive threads = consecutive x
// cells -> each warp scalar-store instr covers 128 contiguous bytes.
// All 8 float4 loads front-batched (MLP=8). Output stores use st.global.cs
// (streaming / evict-first): the 512MB write stream has zero reuse, keep it
// out of L2 so feat/idx lines stay resident.
// ---------------------------------------------------------------------------
__device__ __forceinline__ void stcs(float* p, float v) {
#if __CUDA_ARCH__ >= 320
    __stcs(p, v);
#else
    *p = v;
#endif
}

__global__ __launch_bounds__(256, 5) void gather_kernel(
    const float* __restrict__ feat, float* __restrict__ out)
{
    int t = blockIdx.x * blockDim.x + threadIdx.x;   // 4*TOTAL_CELLS threads
    int q    = t >> 20;                              // quarter: ch [32q, 32q+32)
    int cell = t & (TOTAL_CELLS - 1);

    int p = __ldg(g_idx + cell);                     // coalesced 128B/warp

    const float4* r = (p >= 0)
        ? (const float4*)(feat + (size_t)p * CH + q * QCH)
        : (g_zero_row + q * (QCH / 4));

    // Front-batch all 8 loads (one 128B line per thread)
    float4 v0 = __ldg(r + 0);
    float4 v1 = __ldg(r + 1);
    float4 v2 = __ldg(r + 2);
    float4 v3 = __ldg(r + 3);
    float4 v4 = __ldg(r + 4);
    float4 v5 = __ldg(r + 5);
    float4 v6 = __ldg(r + 6);
    float4 v7 = __ldg(r + 7);

    int b = cell >> 18;                              // batch
    float* o = out + (size_t)(b * CH + q * QCH) * CELLS + (cell & (CELLS - 1));

    stcs(o + (size_t) 0 * CELLS, v0.x);  stcs(o + (size_t) 1 * CELLS, v0.y);
    stcs(o + (size_t) 2 * CELLS, v0.z);  stcs(o + (size_t) 3 * CELLS, v0.w);
    stcs(o + (size_t) 4 * CELLS, v1.x);  stcs(o + (size_t) 5 * CELLS, v1.y);
    stcs(o + (size_t) 6 * CELLS, v1.z);  stcs(o + (size_t) 7 * CELLS, v1.w);
    stcs(o + (size_t) 8 * CELLS, v2.x);  stcs(o + (size_t) 9 * CELLS, v2.y);
    stcs(o + (size_t)10 * CELLS, v2.z);  stcs(o + (size_t)11 * CELLS, v2.w);
    stcs(o + (size_t)12 * CELLS, v3.x);  stcs(o + (size_t)13 * CELLS, v3.y);
    stcs(o + (size_t)14 * CELLS, v3.z);  stcs(o + (size_t)15 * CELLS, v3.w);
    stcs(o + (size_t)16 * CELLS, v4.x);  stcs(o + (size_t)17 * CELLS, v4.y);
    stcs(o + (size_t)18 * CELLS, v4.z);  stcs(o + (size_t)19 * CELLS, v4.w);
    stcs(o + (size_t)20 * CELLS, v5.x);  stcs(o + (size_t)21 * CELLS, v5.y);
    stcs(o + (size_t)22 * CELLS, v5.z);  stcs(o + (size_t)23 * CELLS, v5.w);
    stcs(o + (size_t)24 * CELLS, v6.x);  stcs(o + (size_t)25 * CELLS, v6.y);
    stcs(o + (size_t)26 * CELLS, v6.z);  stcs(o + (size_t)27 * CELLS, v6.w);
    stcs(o + (size_t)28 * CELLS, v7.x);  stcs(o + (size_t)29 * CELLS, v7.y);
    stcs(o + (size_t)30 * CELLS, v7.z);  stcs(o + (size_t)31 * CELLS, v7.w);
}

// ---------------------------------------------------------------------------
// Launch: identify inputs by size (batch_size scalar / features / coords).
// ---------------------------------------------------------------------------
extern "C" void kernel_launch(void* const* d_in, const int* in_sizes, int n_in,
                              void* d_out, int out_size)
{
    // features is the largest input (P*128 floats); coords has P*4 ints.
    int fi = 0;
    long long best = -1;
    for (int i = 0; i < n_in; ++i) {
        if ((long long)in_sizes[i] > best) { best = in_sizes[i]; fi = i; }
    }
    const float* feat = (const float*)d_in[fi];
    int P = in_sizes[fi] / CH;

    const int* coords = nullptr;
    for (int i = 0; i < n_in; ++i) {
        if (i != fi && in_sizes[i] == P * 4) { coords = (const int*)d_in[i]; break; }
    }
    if (!coords) { // fallback: second-largest input
        int ci = -1; long long b2 = -1;
        for (int i = 0; i < n_in; ++i)
            if (i != fi && (long long)in_sizes[i] > b2) { b2 = in_sizes[i]; ci = i; }
        coords = (const int*)d_in[ci];
    }

    float* out = (float*)d_out;

    // Pass 0: reset index canvas to -1 (0xFF bytes). Memset node: capturable.
    void* idx_ptr = nullptr;
    cudaGetSymbolAddress(&idx_ptr, g_idx);
    cudaMemsetAsync(idx_ptr, 0xFF, TOTAL_CELLS * sizeof(int), 0);

    // Pass 1: scatter pillar indices
    build_idx_kernel<<<(P + 255) / 256, 256>>>(coords, P);

    // Pass 2: gather + transpose (4 threads per cell, 32 channels each)
    gather_kernel<<<(4 * TOTAL_CELLS) / 256, 256>>>(feat, out);
}